// round 15
// baseline (speedup 1.0000x reference)
#include <cuda_runtime.h>
#include <cuda_fp16.h>
#include <math.h>
#include <stdint.h>

#define B_      2
#define S_      2048
#define DIM_    1024
#define H_      16
#define KVH_    4
#define HD_     64
#define KVDIM_  256
#define R_      4
#define NSTEPS_ 2
#define M_      (B_*S_)
#define WROWS_  2560   // [0,1024): Wq+lora | [1024,1280): Wk | [1280,1536): Wv+lora | [1536,2560): Wp

#define QSCALE_ (0.125f * 1.4426950408889634f)

typedef unsigned short ushort_t;
typedef unsigned long long ull;

__device__ __forceinline__ uint32_t smem_u32(const void* p) {
    uint32_t a;
    asm("{ .reg .u64 t; cvta.to.shared.u64 t, %1; cvt.u32.u64 %0, t; }" : "=r"(a) : "l"(p));
    return a;
}

#define LDSM4(r, addr) \
    asm volatile("ldmatrix.sync.aligned.m8n8.x4.shared.b16 {%0,%1,%2,%3}, [%4];" \
        : "=r"((r)[0]),"=r"((r)[1]),"=r"((r)[2]),"=r"((r)[3]) : "r"(addr))
#define LDSM4T(r, addr) \
    asm volatile("ldmatrix.sync.aligned.m8n8.x4.trans.shared.b16 {%0,%1,%2,%3}, [%4];" \
        : "=r"((r)[0]),"=r"((r)[1]),"=r"((r)[2]),"=r"((r)[3]) : "r"(addr))

#define MMA_F16(c, a, b0v, b1v) \
    asm volatile("mma.sync.aligned.m16n8k16.row.col.f32.f16.f16.f32 " \
        "{%0,%1,%2,%3}, {%4,%5,%6,%7}, {%8,%9}, {%0,%1,%2,%3};" \
        : "+f"((c)[0]),"+f"((c)[1]),"+f"((c)[2]),"+f"((c)[3]) \
        : "r"((a)[0]),"r"((a)[1]),"r"((a)[2]),"r"((a)[3]), "r"(b0v),"r"(b1v))

#define CP_ASYNC16(dst, src) \
    asm volatile("cp.async.cg.shared.global [%0], [%1], 16;" :: "r"(dst), "l"(src) : "memory")
#define CP_COMMIT() asm volatile("cp.async.commit_group;" ::: "memory")
#define CP_WAIT(n)  asm volatile("cp.async.wait_group %0;" :: "n"(n) : "memory")

__device__ __forceinline__ uint32_t pkhf(float lo, float hi) {
    uint32_t r; asm("cvt.rn.f16x2.f32 %0, %1, %2;" : "=r"(r) : "f"(hi), "f"(lo)); return r;
}

// ---- packed f32x2 helpers ----
__device__ __forceinline__ ull pk2(float x, float y) {
    ull r; asm("mov.b64 %0, {%1, %2};" : "=l"(r) : "f"(x), "f"(y)); return r;
}
__device__ __forceinline__ ull pk2u(uint32_t x, uint32_t y) {
    ull r; asm("mov.b64 %0, {%1, %2};" : "=l"(r) : "r"(x), "r"(y)); return r;
}
__device__ __forceinline__ void up2(float& x, float& y, ull v) {
    asm("mov.b64 {%0, %1}, %2;" : "=f"(x), "=f"(y) : "l"(v));
}
__device__ __forceinline__ void up2u(uint32_t& x, uint32_t& y, ull v) {
    asm("mov.b64 {%0, %1}, %2;" : "=r"(x), "=r"(y) : "l"(v));
}
__device__ __forceinline__ ull add2_(ull a, ull b) {
    ull d; asm("add.rn.f32x2 %0, %1, %2;" : "=l"(d) : "l"(a), "l"(b)); return d;
}
__device__ __forceinline__ ull mul2_(ull a, ull b) {
    ull d; asm("mul.rn.f32x2 %0, %1, %2;" : "=l"(d) : "l"(a), "l"(b)); return d;
}
__device__ __forceinline__ ull fma2_(ull a, ull b, ull c) {
    ull d; asm("fma.rn.f32x2 %0, %1, %2, %3;" : "=l"(d) : "l"(a), "l"(b), "l"(c)); return d;
}

// ---------------- scratch ----------------
__device__ ushort_t g_xf[M_*DIM_];
__device__ ushort_t g_yf[M_*DIM_];
__device__ ushort_t g_whf[WROWS_*DIM_];
__device__ ushort_t g_qf[M_*DIM_];
__device__ ushort_t g_kf[M_*KVDIM_];
__device__ ushort_t g_vf[M_*KVDIM_];
__device__ float    g_rope[S_*16*2];   // [s][i] -> (cos, sin)

// ---------------- fused prep ----------------
#define NBW_ ((WROWS_*256)/256)
#define NBX_ ((M_*DIM_/4)/256)
#define NBR_ ((S_*16+255)/256)
__global__ void prep_all_kernel(const float* __restrict__ x,
                                const float* __restrict__ Wq, const float* __restrict__ Wk,
                                const float* __restrict__ Wv, const float* __restrict__ Wp,
                                const float* __restrict__ Aq, const float* __restrict__ Bq,
                                const float* __restrict__ Av, const float* __restrict__ Bv,
                                const int*   __restrict__ stepp) {
    int blk = blockIdx.x;
    if (blk < NBW_) {
        int t = blk * 256 + threadIdx.x;
        int row = t >> 8, k4 = t & 255;
        int step = *stepp;
        bool ok = (step >= 0 && step < NSTEPS_);
        float4 w;
        if (row < 1024) {
            w = ((const float4*)(Wq + (size_t)row * DIM_))[k4];
            if (ok) {
                const float* Ab = Aq + (size_t)step * R_ * DIM_;
                const float* Bb = Bq + ((size_t)step * DIM_ + row) * R_;
                #pragma unroll
                for (int r = 0; r < R_; r++) {
                    float b = Bb[r];
                    float4 a = ((const float4*)(Ab + (size_t)r * DIM_))[k4];
                    w.x += b*a.x; w.y += b*a.y; w.z += b*a.z; w.w += b*a.w;
                }
            }
        } else if (row < 1280) {
            w = ((const float4*)(Wk + (size_t)(row - 1024) * DIM_))[k4];
        } else if (row < 1536) {
            int vr = row - 1280;
            w = ((const float4*)(Wv + (size_t)vr * DIM_))[k4];
            if (ok) {
                const float* Ab = Av + (size_t)step * R_ * DIM_;
                const float* Bb = Bv + ((size_t)step * KVDIM_ + vr) * R_;
                #pragma unroll
                for (int r = 0; r < R_; r++) {
                    float b = Bb[r];
                    float4 a = ((const float4*)(Ab + (size_t)r * DIM_))[k4];
                    w.x += b*a.x; w.y += b*a.y; w.z += b*a.z; w.w += b*a.w;
                }
            }
        } else {
            w = ((const float4*)(Wp + (size_t)(row - 1536) * DIM_))[k4];
        }
        uint2 hp;
        hp.x = pkhf(w.x, w.y);
        hp.y = pkhf(w.z, w.w);
        ((uint2*)g_whf)[t] = hp;
    } else if (blk < NBW_ + NBX_) {
        int t = (blk - NBW_) * 256 + threadIdx.x;
        float4 v = ((const float4*)x)[t];
        uint2 o;
        o.x = pkhf(v.x, v.y);
        o.y = pkhf(v.z, v.w);
        ((uint2*)g_xf)[t] = o;
    } else {
        int t = (blk - NBW_ - NBX_) * 256 + threadIdx.x;
        if (t < S_ * 16) {
            int s = t >> 4, i = t & 15;
            float invf = exp2f(-0.83048202372184059f * (float)i);
            float ang = (float)s * invf;
            g_rope[t * 2]     = cosf(ang);
            g_rope[t * 2 + 1] = sinf(ang);
        }
    }
}

// ---------------- fp16 GEMM, 3 stages, 3 CTAs/SM, fused RMS+RoPE epilogue ----------------
#define GT_      10240            // 128 rows x 80B
#define GSTAGE_  (2*GT_)
#define G_SMEM   (3*GSTAGE_)      // 61440 -> 3 CTAs/SM

template<int MODE>
__global__ void __launch_bounds__(128, 3)
gemm_mma_kernel(const float* __restrict__ gainp, float* __restrict__ outp) {
    extern __shared__ char smem[];
    uint32_t sb = smem_u32(smem);
    constexpr int WOFF = (MODE == 0) ? 0 : 1536;
    const ushort_t* Xf = (MODE == 2) ? g_yf : g_xf;

    int m0 = blockIdx.y * 128, n0 = blockIdx.x * 128;
    int tid = threadIdx.x;
    int wid = tid >> 5, lane = tid & 31;
    int wm = (wid >> 1) * 64, wn = (wid & 1) * 64;
    int lrow = (lane & 7) + ((lane >> 3) & 1) * 8;
    int lcol = (lane >> 4) * 8;

    auto load_stage = [&](int it, int s) {
        int k0 = it * 32;
        int q = tid & 3;
        int r0 = tid >> 2;
        #pragma unroll
        for (int t = 0; t < 8; t++) {
            int tile = t >> 2;
            int row = (t & 3) * 32 + r0;
            const ushort_t* src;
            if (tile == 0) src = Xf    + (size_t)(m0 + row) * DIM_ + k0 + q * 8;
            else           src = g_whf + (size_t)(WOFF + n0 + row) * DIM_ + k0 + q * 8;
            CP_ASYNC16(sb + s * GSTAGE_ + tile * GT_ + row * 80 + q * 16, src);
        }
        CP_COMMIT();
    };

    float c[4][8][4];
    #pragma unroll
    for (int i = 0; i < 4; i++)
        #pragma unroll
        for (int j = 0; j < 8; j++)
            #pragma unroll
            for (int p = 0; p < 4; p++) c[i][j][p] = 0.f;

    load_stage(0, 0);
    load_stage(1, 1);

    int slot = 2;
    for (int it = 0; it < 32; it++) {
        if (it < 31) CP_WAIT(1);
        else         CP_WAIT(0);
        __syncthreads();
        if (it + 2 < 32) load_stage(it + 2, slot);
        if (++slot == 3) slot = 0;

        uint32_t base = sb + (it % 3) * GSTAGE_;

        #pragma unroll
        for (int ks = 0; ks < 2; ks++) {
            int kb = ks * 16;
            uint32_t a[4][4];
            #pragma unroll
            for (int mf = 0; mf < 4; mf++)
                LDSM4(a[mf], base + (wm + mf * 16 + lrow) * 80 + (kb + lcol) * 2);
            uint32_t bb[2][4];
            LDSM4(bb[0], base + GT_ + (wn + lrow) * 80 + (kb + lcol) * 2);
            #pragma unroll
            for (int nt = 0; nt < 4; nt++) {
                int cur = nt & 1;
                if (nt < 3)
                    LDSM4(bb[cur ^ 1], base + GT_ + (wn + (nt+1) * 16 + lrow) * 80 + (kb + lcol) * 2);
                #pragma unroll
                for (int mf = 0; mf < 4; mf++) {
                    MMA_F16(c[mf][nt*2],   a[mf], bb[cur][0], bb[cur][2]);
                    MMA_F16(c[mf][nt*2+1], a[mf], bb[cur][1], bb[cur][3]);
                }
            }
        }
    }

    if (MODE == 2) {
        #pragma unroll
        for (int mf = 0; mf < 4; mf++) {
            #pragma unroll
            for (int nf = 0; nf < 8; nf++) {
                int gr = m0 + wm + mf * 16 + (lane >> 2);
                int gc = n0 + wn + nf * 8 + (lane & 3) * 2;
                *(float2*)&outp[(size_t)gr * 1024 + gc]       = make_float2(c[mf][nf][0], c[mf][nf][1]);
                *(float2*)&outp[(size_t)(gr + 8) * 1024 + gc] = make_float2(c[mf][nf][2], c[mf][nf][3]);
            }
        }
        return;
    }

    int nglob = n0 + wn;
    if (nglob >= 1280) {
        #pragma unroll
        for (int mf = 0; mf < 4; mf++) {
            #pragma unroll
            for (int nf = 0; nf < 8; nf++) {
                int gr = m0 + wm + mf * 16 + (lane >> 2);
                int vc = nglob - 1280 + nf * 8 + (lane & 3) * 2;
                *(uint32_t*)&g_vf[(size_t)gr * 256 + vc]       = pkhf(c[mf][nf][0], c[mf][nf][1]);
                *(uint32_t*)&g_vf[(size_t)(gr + 8) * 256 + vc] = pkhf(c[mf][nf][2], c[mf][nf][3]);
            }
        }
        return;
    }

    bool isQ = (nglob < 1024);
    float gsc = isQ ? (gainp[nglob >> 6] * QSCALE_) : 1.0f;
    int q2 = (lane & 3) * 2;

    #pragma unroll
    for (int mf = 0; mf < 4; mf++) {
        #pragma unroll
        for (int rr = 0; rr < 2; rr++) {
            float v[8][2];
            #pragma unroll
            for (int nf = 0; nf < 8; nf++) {
                v[nf][0] = c[mf][nf][rr * 2];
                v[nf][1] = c[mf][nf][rr * 2 + 1];
            }
            float ss = 0.f;
            #pragma unroll
            for (int nf = 0; nf < 8; nf++)
                ss += v[nf][0] * v[nf][0] + v[nf][1] * v[nf][1];
            ss += __shfl_xor_sync(0xffffffffu, ss, 1);
            ss += __shfl_xor_sync(0xffffffffu, ss, 2);
            float scl = rsqrtf(ss * (1.0f / 64.0f) + 1.1920929e-7f) * gsc;
            #pragma unroll
            for (int nf = 0; nf < 8; nf++) { v[nf][0] *= scl; v[nf][1] *= scl; }

            int m = m0 + wm + mf * 16 + (lane >> 2) + rr * 8;
            int s = m & (S_ - 1);
            float4 r0 = *(const float4*)&g_rope[(s * 16 + q2) * 2];
            float4 r1 = *(const float4*)&g_rope[(s * 16 + 8 + q2) * 2];
            float x1, x2;
            x1 = v[0][0]; x2 = v[2][0];
            v[0][0] = x1 * r0.x + x2 * r0.y;  v[2][0] = -x1 * r0.y + x2 * r0.x;
            x1 = v[0][1]; x2 = v[2][1];
            v[0][1] = x1 * r0.z + x2 * r0.w;  v[2][1] = -x1 * r0.w + x2 * r0.z;
            x1 = v[1][0]; x2 = v[3][0];
            v[1][0] = x1 * r1.x + x2 * r1.y;  v[3][0] = -x1 * r1.y + x2 * r1.x;
            x1 = v[1][1]; x2 = v[3][1];
            v[1][1] = x1 * r1.z + x2 * r1.w;  v[3][1] = -x1 * r1.w + x2 * r1.z;

            if (isQ) {
                size_t bix = (size_t)m * 1024 + nglob + q2;
                #pragma unroll
                for (int nf = 0; nf < 8; nf++)
                    *(uint32_t*)&g_qf[bix + nf * 8] = pkhf(v[nf][0], v[nf][1]);
            } else {
                size_t bix = (size_t)m * 256 + (nglob - 1024) + q2;
                #pragma unroll
                for (int nf = 0; nf < 8; nf++)
                    *(uint32_t*)&g_kf[bix + nf * 8] = pkhf(v[nf][0], v[nf][1]);
            }
        }
    }
}

// ---------------- flash attention: padded rows, 2 CTAs/SM (R12 config + P-pack) ----------------
#define FA_TILE  18432
#define FA_STG   (2*FA_TILE)
#define FA_SMEM  (2*FA_STG)    // 73728
#define MASKV_   (-50.0f)

__global__ void __launch_bounds__(128, 2)
flash_mma_kernel() {
    extern __shared__ char smem[];
    uint32_t sb = smem_u32(smem);

    int b = blockIdx.z, h = blockIdx.y;
    int q0 = (gridDim.x - 1 - blockIdx.x) * 128;
    int kvh = h >> 2;
    int tid = threadIdx.x;
    int wid = tid >> 5, lane = tid & 31;
    int r = lane >> 2, c2 = (lane & 3) * 2;
    int lrow = (lane & 7) + ((lane >> 3) & 1) * 8;
    int lcol = (lane >> 4) * 8;

    int wq = wid * 32;
    int qmaxw = q0 + wq + 31;

    size_t tok[2][2];
    #pragma unroll
    for (int mf = 0; mf < 2; mf++) {
        tok[mf][0] = (size_t)(b * S_) + q0 + wq + mf * 16 + r;
        tok[mf][1] = tok[mf][0] + 8;
    }

    uint32_t qf[2][4][4];
    #pragma unroll
    for (int mf = 0; mf < 2; mf++)
        #pragma unroll
        for (int t = 0; t < 4; t++) {
            size_t c0 = (size_t)h * 64 + t * 16 + c2;
            qf[mf][t][0] = *(const uint32_t*)&g_qf[tok[mf][0] * 1024 + c0];
            qf[mf][t][1] = *(const uint32_t*)&g_qf[tok[mf][1] * 1024 + c0];
            qf[mf][t][2] = *(const uint32_t*)&g_qf[tok[mf][0] * 1024 + c0 + 8];
            qf[mf][t][3] = *(const uint32_t*)&g_qf[tok[mf][1] * 1024 + c0 + 8];
        }

    float oc[2][8][4];
    #pragma unroll
    for (int mf = 0; mf < 2; mf++)
        #pragma unroll
        for (int j = 0; j < 8; j++)
            #pragma unroll
            for (int p = 0; p < 4; p++) oc[mf][j][p] = 0.f;
    float lrw[2][2] = {{0.f, 0.f}, {0.f, 0.f}};

    const ull MAGIC2  = pk2(12582912.f, 12582912.f);
    const ull NMAGIC2 = pk2(-12582912.f, -12582912.f);
    const ull NONE2   = pk2(-1.f, -1.f);
    const ull ONE2    = pk2(1.f, 1.f);
    const ull EC1 = pk2(0.69314718f,  0.69314718f);
    const ull EC2 = pk2(0.24022651f,  0.24022651f);
    const ull EC3 = pk2(0.055504109f, 0.055504109f);
    const ull EC4 = pk2(0.0096181291f, 0.0096181291f);

    auto exp2pair = [&](float y0, float y1, float& e0, float& e1) {
        ull y = pk2(y0, y1);
        ull t = add2_(y, MAGIC2);
        ull rr_ = add2_(t, NMAGIC2);
        ull f = fma2_(rr_, NONE2, y);
        ull p = fma2_(EC4, f, EC3);
        p = fma2_(p, f, EC2);
        p = fma2_(p, f, EC1);
        p = fma2_(p, f, ONE2);
        uint32_t tl, th; up2u(tl, th, t);
        ull es = pk2u((tl << 23) + 0x3F800000u, (th << 23) + 0x3F800000u);
        ull res = mul2_(p, es);
        up2(e0, e1, res);
    };

    int q8 = tid & 7, rr = tid >> 3;

    auto load_tile = [&](int j0, int s) {
        #pragma unroll
        for (int p = 0; p < 8; p++) {
            int row = p * 16 + rr;
            size_t gsrc = (size_t)(b * S_ + j0 + row) * 256 + kvh * 64 + q8 * 8;
            CP_ASYNC16(sb + s * FA_STG + row * 144 + q8 * 16, g_kf + gsrc);
            CP_ASYNC16(sb + s * FA_STG + FA_TILE + row * 144 + q8 * 16, g_vf + gsrc);
        }
        CP_COMMIT();
    };

    load_tile(0, 0);

    for (int j0 = 0; j0 <= q0; j0 += 128) {
        int buf = (j0 >> 7) & 1;
        CP_WAIT(0);
        __syncthreads();
        if (j0 + 128 <= q0) load_tile(j0 + 128, buf ^ 1);

        uint32_t kbank = sb + buf * FA_STG;
        uint32_t vbank = kbank + FA_TILE;

        #pragma unroll
        for (int half = 0; half < 2; half++) {
            int kg0 = j0 + half * 64;
            bool active = (kg0 <= qmaxw);
            int ks = half * 64;

            if (active) {
                float sc[2][8][4];
                #pragma unroll
                for (int mf = 0; mf < 2; mf++)
                    #pragma unroll
                    for (int j = 0; j < 8; j++)
                        #pragma unroll
                        for (int p = 0; p < 4; p++) sc[mf][j][p] = 0.f;

                // scores = Q.K^T with bk register chain (prefetch 1 ahead)
                {
                    uint32_t bkb[2][4];
                    LDSM4(bkb[0], kbank + (ks + lrow) * 144 + lcol * 2);
                    #pragma unroll
                    for (int u = 0; u < 16; u++) {
                        int nt = u >> 2, t = u & 3;
                        int cur = u & 1;
                        if (u < 15) {
                            int un = u + 1;
                            int ntn = un >> 2, tn = un & 3;
                            LDSM4(bkb[cur ^ 1], kbank + (ks + ntn * 16 + lrow) * 144 + (tn * 16 + lcol) * 2);
                        }
                        #pragma unroll
                        for (int mf = 0; mf < 2; mf++) {
                            MMA_F16(sc[mf][nt*2],   qf[mf][t], bkb[cur][0], bkb[cur][2]);
                            MMA_F16(sc[mf][nt*2+1], qf[mf][t], bkb[cur][1], bkb[cur][3]);
                        }
                    }
                }

                if (kg0 + 63 > q0 + wq) {
                    #pragma unroll
                    for (int mf = 0; mf < 2; mf++) {
                        int qg0 = q0 + wq + mf * 16 + r;
                        int qg1 = qg0 + 8;
                        #pragma unroll
                        for (int j = 0; j < 8; j++) {
                            int key = kg0 + 8 * j + c2;
                            if (key     > qg0) sc[mf][j][0] = MASKV_;
                            if (key + 1 > qg0) sc[mf][j][1] = MASKV_;
                            if (key     > qg1) sc[mf][j][2] = MASKV_;
                            if (key + 1 > qg1) sc[mf][j][3] = MASKV_;
                        }
                    }
                }

                // p = exp2(s); pack to fp16 immediately (frees sc regs)
                uint32_t ph[2][8][2];
                #pragma unroll
                for (int mf = 0; mf < 2; mf++) {
                    float rs0 = 0.f, rs1 = 0.f;
                    #pragma unroll
                    for (int j = 0; j < 8; j++) {
                        float e0, e1, e2, e3;
                        exp2pair(sc[mf][j][0], sc[mf][j][1], e0, e1);
                        exp2pair(sc[mf][j][2], sc[mf][j][3], e2, e3);
                        rs0 += e0 + e1;
                        rs1 += e2 + e3;
                        ph[mf][j][0] = pkhf(e0, e1);
                        ph[mf][j][1] = pkhf(e2, e3);
                    }
                    lrw[mf][0] += rs0;
                    lrw[mf][1] += rs1;
                }

                // O += P @ V
                #pragma unroll
                for (int u = 0; u < 4; u++) {
                    #pragma unroll
                    for (int dv = 0; dv < 4; dv++) {
                        uint32_t vv[4];
                        LDSM4T(vv, vbank + (ks + u * 16 + (lane & 15)) * 144
                                   + (dv * 16 + (lane >> 4) * 8) * 2);
                        #pragma unroll
                        for (int mf = 0; mf < 2; mf++) {
                            uint32_t A0[4] = {ph[mf][2*u][0], ph[mf][2*u][1],
                                              ph[mf][2*u+1][0], ph[mf][2*u+1][1]};
                            MMA_F16(oc[mf][dv*2],   A0, vv[0], vv[1]);
                            MMA_F16(oc[mf][dv*2+1], A0, vv[2], vv[3]);
                        }
                    }
                }
            }
        }
    }

    #pragma unroll
    for (int mf = 0; mf < 2; mf++) {
        #pragma unroll
        for (int rh = 0; rh < 2; rh++) {
            float l = lrw[mf][rh];
            l += __shfl_xor_sync(0xffffffffu, l, 1);
            l += __shfl_xor_sync(0xffffffffu, l, 2);
            lrw[mf][rh] = 1.0f / l;
        }
        #pragma unroll
        for (int j = 0; j < 8; j++) {
            size_t col = (size_t)h * 64 + 8 * j + c2;
            *(uint32_t*)&g_yf[tok[mf][0] * 1024 + col] =
                pkhf(oc[mf][j][0] * lrw[mf][0], oc[mf][j][1] * lrw[mf][0]);
            *(uint32_t*)&g_yf[tok[mf][1] * 1024 + col] =
                pkhf(oc[mf][j][2] * lrw[mf][1], oc[mf][j][3] * lrw[mf][1]);
        }
    }
}

// ---------------- launch ----------------
extern "C" void kernel_launch(void* const* d_in, const int* in_sizes, int n_in,
                              void* d_out, int out_size) {
    const float* x    = (const float*)d_in[0];
    const float* Wq   = (const float*)d_in[1];
    const float* Wk   = (const float*)d_in[2];
    const float* Wv   = (const float*)d_in[3];
    const float* Wp   = (const float*)d_in[4];
    const float* gain = (const float*)d_in[5];
    const float* Aq   = (const float*)d_in[6];
    const float* Bq   = (const float*)d_in[7];
    const float* Av   = (const float*)d_in[8];
    const float* Bv   = (const float*)d_in[9];
    const int*   step = (const int*)d_in[10];
    float* out = (float*)d_out;

    prep_all_kernel<<<NBW_ + NBX_ + NBR_, 256>>>(x, Wq, Wk, Wv, Wp, Aq, Bq, Av, Bv, step);

    cudaFuncSetAttribute(gemm_mma_kernel<0>, cudaFuncAttributeMaxDynamicSharedMemorySize, G_SMEM);
    cudaFuncSetAttribute(gemm_mma_kernel<2>, cudaFuncAttributeMaxDynamicSharedMemorySize, G_SMEM);
    cudaFuncSetAttribute(flash_mma_kernel,   cudaFuncAttributeMaxDynamicSharedMemorySize, FA_SMEM);

    gemm_mma_kernel<0><<<dim3(1536/128, M_/128), 128, G_SMEM>>>(gain, nullptr);

    flash_mma_kernel<<<dim3(S_/128, H_, B_), 128, FA_SMEM>>>();

    gemm_mma_kernel<2><<<dim3(1024/128, M_/128), 128, G_SMEM>>>(gain, out);
}

// round 16
// speedup vs baseline: 1.5527x; 1.5527x over previous
#include <cuda_runtime.h>
#include <cuda_fp16.h>
#include <math.h>
#include <stdint.h>

#define B_      2
#define S_      2048
#define DIM_    1024
#define H_      16
#define KVH_    4
#define HD_     64
#define KVDIM_  256
#define R_      4
#define NSTEPS_ 2
#define M_      (B_*S_)
#define WROWS_  2560   // [0,1024): Wq+lora | [1024,1280): Wk | [1280,1536): Wv+lora | [1536,2560): Wp

#define QSCALE_ (0.125f * 1.4426950408889634f)

typedef unsigned short ushort_t;
typedef unsigned long long ull;

__device__ __forceinline__ uint32_t smem_u32(const void* p) {
    uint32_t a;
    asm("{ .reg .u64 t; cvta.to.shared.u64 t, %1; cvt.u32.u64 %0, t; }" : "=r"(a) : "l"(p));
    return a;
}

#define LDSM4(r, addr) \
    asm volatile("ldmatrix.sync.aligned.m8n8.x4.shared.b16 {%0,%1,%2,%3}, [%4];" \
        : "=r"((r)[0]),"=r"((r)[1]),"=r"((r)[2]),"=r"((r)[3]) : "r"(addr))
#define LDSM4T(r, addr) \
    asm volatile("ldmatrix.sync.aligned.m8n8.x4.trans.shared.b16 {%0,%1,%2,%3}, [%4];" \
        : "=r"((r)[0]),"=r"((r)[1]),"=r"((r)[2]),"=r"((r)[3]) : "r"(addr))

#define MMA_F16(c, a, b0v, b1v) \
    asm volatile("mma.sync.aligned.m16n8k16.row.col.f32.f16.f16.f32 " \
        "{%0,%1,%2,%3}, {%4,%5,%6,%7}, {%8,%9}, {%0,%1,%2,%3};" \
        : "+f"((c)[0]),"+f"((c)[1]),"+f"((c)[2]),"+f"((c)[3]) \
        : "r"((a)[0]),"r"((a)[1]),"r"((a)[2]),"r"((a)[3]), "r"(b0v),"r"(b1v))

#define CP_ASYNC16(dst, src) \
    asm volatile("cp.async.cg.shared.global [%0], [%1], 16;" :: "r"(dst), "l"(src) : "memory")
#define CP_COMMIT() asm volatile("cp.async.commit_group;" ::: "memory")
#define CP_WAIT(n)  asm volatile("cp.async.wait_group %0;" :: "n"(n) : "memory")

__device__ __forceinline__ uint32_t pkhf(float lo, float hi) {
    uint32_t r; asm("cvt.rn.f16x2.f32 %0, %1, %2;" : "=r"(r) : "f"(hi), "f"(lo)); return r;
}

// ---- packed f32x2 helpers ----
__device__ __forceinline__ ull pk2(float x, float y) {
    ull r; asm("mov.b64 %0, {%1, %2};" : "=l"(r) : "f"(x), "f"(y)); return r;
}
__device__ __forceinline__ ull pk2u(uint32_t x, uint32_t y) {
    ull r; asm("mov.b64 %0, {%1, %2};" : "=l"(r) : "r"(x), "r"(y)); return r;
}
__device__ __forceinline__ void up2(float& x, float& y, ull v) {
    asm("mov.b64 {%0, %1}, %2;" : "=f"(x), "=f"(y) : "l"(v));
}
__device__ __forceinline__ void up2u(uint32_t& x, uint32_t& y, ull v) {
    asm("mov.b64 {%0, %1}, %2;" : "=r"(x), "=r"(y) : "l"(v));
}
__device__ __forceinline__ ull add2_(ull a, ull b) {
    ull d; asm("add.rn.f32x2 %0, %1, %2;" : "=l"(d) : "l"(a), "l"(b)); return d;
}
__device__ __forceinline__ ull mul2_(ull a, ull b) {
    ull d; asm("mul.rn.f32x2 %0, %1, %2;" : "=l"(d) : "l"(a), "l"(b)); return d;
}
__device__ __forceinline__ ull fma2_(ull a, ull b, ull c) {
    ull d; asm("fma.rn.f32x2 %0, %1, %2, %3;" : "=l"(d) : "l"(a), "l"(b), "l"(c)); return d;
}

// ---------------- scratch ----------------
__device__ ushort_t g_xf[M_*DIM_];
__device__ ushort_t g_yf[M_*DIM_];
__device__ ushort_t g_whf[WROWS_*DIM_];
__device__ ushort_t g_qf[M_*DIM_];
__device__ ushort_t g_kf[M_*KVDIM_];
__device__ ushort_t g_vf[M_*KVDIM_];
__device__ float    g_rope[S_*16*2];   // [s][i] -> (cos, sin)

// ---------------- fused prep ----------------
#define NBW_ ((WROWS_*256)/256)
#define NBX_ ((M_*DIM_/4)/256)
#define NBR_ ((S_*16+255)/256)
__global__ void prep_all_kernel(const float* __restrict__ x,
                                const float* __restrict__ Wq, const float* __restrict__ Wk,
                                const float* __restrict__ Wv, const float* __restrict__ Wp,
                                const float* __restrict__ Aq, const float* __restrict__ Bq,
                                const float* __restrict__ Av, const float* __restrict__ Bv,
                                const int*   __restrict__ stepp) {
    int blk = blockIdx.x;
    if (blk < NBW_) {
        int t = blk * 256 + threadIdx.x;
        int row = t >> 8, k4 = t & 255;
        int step = *stepp;
        bool ok = (step >= 0 && step < NSTEPS_);
        float4 w;
        if (row < 1024) {
            w = ((const float4*)(Wq + (size_t)row * DIM_))[k4];
            if (ok) {
                const float* Ab = Aq + (size_t)step * R_ * DIM_;
                const float* Bb = Bq + ((size_t)step * DIM_ + row) * R_;
                #pragma unroll
                for (int r = 0; r < R_; r++) {
                    float b = Bb[r];
                    float4 a = ((const float4*)(Ab + (size_t)r * DIM_))[k4];
                    w.x += b*a.x; w.y += b*a.y; w.z += b*a.z; w.w += b*a.w;
                }
            }
        } else if (row < 1280) {
            w = ((const float4*)(Wk + (size_t)(row - 1024) * DIM_))[k4];
        } else if (row < 1536) {
            int vr = row - 1280;
            w = ((const float4*)(Wv + (size_t)vr * DIM_))[k4];
            if (ok) {
                const float* Ab = Av + (size_t)step * R_ * DIM_;
                const float* Bb = Bv + ((size_t)step * KVDIM_ + vr) * R_;
                #pragma unroll
                for (int r = 0; r < R_; r++) {
                    float b = Bb[r];
                    float4 a = ((const float4*)(Ab + (size_t)r * DIM_))[k4];
                    w.x += b*a.x; w.y += b*a.y; w.z += b*a.z; w.w += b*a.w;
                }
            }
        } else {
            w = ((const float4*)(Wp + (size_t)(row - 1536) * DIM_))[k4];
        }
        uint2 hp;
        hp.x = pkhf(w.x, w.y);
        hp.y = pkhf(w.z, w.w);
        ((uint2*)g_whf)[t] = hp;
    } else if (blk < NBW_ + NBX_) {
        int t = (blk - NBW_) * 256 + threadIdx.x;
        float4 v = ((const float4*)x)[t];
        uint2 o;
        o.x = pkhf(v.x, v.y);
        o.y = pkhf(v.z, v.w);
        ((uint2*)g_xf)[t] = o;
    } else {
        int t = (blk - NBW_ - NBX_) * 256 + threadIdx.x;
        if (t < S_ * 16) {
            int s = t >> 4, i = t & 15;
            float invf = exp2f(-0.83048202372184059f * (float)i);
            float ang = (float)s * invf;
            g_rope[t * 2]     = cosf(ang);
            g_rope[t * 2 + 1] = sinf(ang);
        }
    }
}

// ---------------- fp16 GEMM, 3 stages, 3 CTAs/SM, fused RMS+RoPE epilogue ----------------
#define GT_      10240            // 128 rows x 80B
#define GSTAGE_  (2*GT_)
#define G_SMEM   (3*GSTAGE_)      // 61440 -> 3 CTAs/SM

template<int MODE>
__global__ void __launch_bounds__(128, 3)
gemm_mma_kernel(const float* __restrict__ gainp, float* __restrict__ outp) {
    extern __shared__ char smem[];
    uint32_t sb = smem_u32(smem);
    constexpr int WOFF = (MODE == 0) ? 0 : 1536;
    const ushort_t* Xf = (MODE == 2) ? g_yf : g_xf;

    int m0 = blockIdx.y * 128, n0 = blockIdx.x * 128;
    int tid = threadIdx.x;
    int wid = tid >> 5, lane = tid & 31;
    int wm = (wid >> 1) * 64, wn = (wid & 1) * 64;
    int lrow = (lane & 7) + ((lane >> 3) & 1) * 8;
    int lcol = (lane >> 4) * 8;

    auto load_stage = [&](int it, int s) {
        int k0 = it * 32;
        int q = tid & 3;
        int r0 = tid >> 2;
        #pragma unroll
        for (int t = 0; t < 8; t++) {
            int tile = t >> 2;
            int row = (t & 3) * 32 + r0;
            const ushort_t* src;
            if (tile == 0) src = Xf    + (size_t)(m0 + row) * DIM_ + k0 + q * 8;
            else           src = g_whf + (size_t)(WOFF + n0 + row) * DIM_ + k0 + q * 8;
            CP_ASYNC16(sb + s * GSTAGE_ + tile * GT_ + row * 80 + q * 16, src);
        }
        CP_COMMIT();
    };

    float c[4][8][4];
    #pragma unroll
    for (int i = 0; i < 4; i++)
        #pragma unroll
        for (int j = 0; j < 8; j++)
            #pragma unroll
            for (int p = 0; p < 4; p++) c[i][j][p] = 0.f;

    load_stage(0, 0);
    load_stage(1, 1);

    int slot = 2;
    for (int it = 0; it < 32; it++) {
        if (it < 31) CP_WAIT(1);
        else         CP_WAIT(0);
        __syncthreads();
        if (it + 2 < 32) load_stage(it + 2, slot);
        if (++slot == 3) slot = 0;

        uint32_t base = sb + (it % 3) * GSTAGE_;

        #pragma unroll
        for (int ks = 0; ks < 2; ks++) {
            int kb = ks * 16;
            uint32_t a[4][4];
            #pragma unroll
            for (int mf = 0; mf < 4; mf++)
                LDSM4(a[mf], base + (wm + mf * 16 + lrow) * 80 + (kb + lcol) * 2);
            uint32_t bb[2][4];
            LDSM4(bb[0], base + GT_ + (wn + lrow) * 80 + (kb + lcol) * 2);
            #pragma unroll
            for (int nt = 0; nt < 4; nt++) {
                int cur = nt & 1;
                if (nt < 3)
                    LDSM4(bb[cur ^ 1], base + GT_ + (wn + (nt+1) * 16 + lrow) * 80 + (kb + lcol) * 2);
                #pragma unroll
                for (int mf = 0; mf < 4; mf++) {
                    MMA_F16(c[mf][nt*2],   a[mf], bb[cur][0], bb[cur][2]);
                    MMA_F16(c[mf][nt*2+1], a[mf], bb[cur][1], bb[cur][3]);
                }
            }
        }
    }

    if (MODE == 2) {
        #pragma unroll
        for (int mf = 0; mf < 4; mf++) {
            #pragma unroll
            for (int nf = 0; nf < 8; nf++) {
                int gr = m0 + wm + mf * 16 + (lane >> 2);
                int gc = n0 + wn + nf * 8 + (lane & 3) * 2;
                *(float2*)&outp[(size_t)gr * 1024 + gc]       = make_float2(c[mf][nf][0], c[mf][nf][1]);
                *(float2*)&outp[(size_t)(gr + 8) * 1024 + gc] = make_float2(c[mf][nf][2], c[mf][nf][3]);
            }
        }
        return;
    }

    int nglob = n0 + wn;
    if (nglob >= 1280) {
        #pragma unroll
        for (int mf = 0; mf < 4; mf++) {
            #pragma unroll
            for (int nf = 0; nf < 8; nf++) {
                int gr = m0 + wm + mf * 16 + (lane >> 2);
                int vc = nglob - 1280 + nf * 8 + (lane & 3) * 2;
                *(uint32_t*)&g_vf[(size_t)gr * 256 + vc]       = pkhf(c[mf][nf][0], c[mf][nf][1]);
                *(uint32_t*)&g_vf[(size_t)(gr + 8) * 256 + vc] = pkhf(c[mf][nf][2], c[mf][nf][3]);
            }
        }
        return;
    }

    bool isQ = (nglob < 1024);
    float gsc = isQ ? (gainp[nglob >> 6] * QSCALE_) : 1.0f;
    int q2 = (lane & 3) * 2;

    #pragma unroll
    for (int mf = 0; mf < 4; mf++) {
        #pragma unroll
        for (int rr = 0; rr < 2; rr++) {
            float v[8][2];
            #pragma unroll
            for (int nf = 0; nf < 8; nf++) {
                v[nf][0] = c[mf][nf][rr * 2];
                v[nf][1] = c[mf][nf][rr * 2 + 1];
            }
            float ss = 0.f;
            #pragma unroll
            for (int nf = 0; nf < 8; nf++)
                ss += v[nf][0] * v[nf][0] + v[nf][1] * v[nf][1];
            ss += __shfl_xor_sync(0xffffffffu, ss, 1);
            ss += __shfl_xor_sync(0xffffffffu, ss, 2);
            float scl = rsqrtf(ss * (1.0f / 64.0f) + 1.1920929e-7f) * gsc;
            #pragma unroll
            for (int nf = 0; nf < 8; nf++) { v[nf][0] *= scl; v[nf][1] *= scl; }

            int m = m0 + wm + mf * 16 + (lane >> 2) + rr * 8;
            int s = m & (S_ - 1);
            float4 r0 = *(const float4*)&g_rope[(s * 16 + q2) * 2];
            float4 r1 = *(const float4*)&g_rope[(s * 16 + 8 + q2) * 2];
            float x1, x2;
            x1 = v[0][0]; x2 = v[2][0];
            v[0][0] = x1 * r0.x + x2 * r0.y;  v[2][0] = -x1 * r0.y + x2 * r0.x;
            x1 = v[0][1]; x2 = v[2][1];
            v[0][1] = x1 * r0.z + x2 * r0.w;  v[2][1] = -x1 * r0.w + x2 * r0.z;
            x1 = v[1][0]; x2 = v[3][0];
            v[1][0] = x1 * r1.x + x2 * r1.y;  v[3][0] = -x1 * r1.y + x2 * r1.x;
            x1 = v[1][1]; x2 = v[3][1];
            v[1][1] = x1 * r1.z + x2 * r1.w;  v[3][1] = -x1 * r1.w + x2 * r1.z;

            if (isQ) {
                size_t bix = (size_t)m * 1024 + nglob + q2;
                #pragma unroll
                for (int nf = 0; nf < 8; nf++)
                    *(uint32_t*)&g_qf[bix + nf * 8] = pkhf(v[nf][0], v[nf][1]);
            } else {
                size_t bix = (size_t)m * 256 + (nglob - 1024) + q2;
                #pragma unroll
                for (int nf = 0; nf < 8; nf++)
                    *(uint32_t*)&g_kf[bix + nf * 8] = pkhf(v[nf][0], v[nf][1]);
            }
        }
    }
}

// ---------------- flash attention: padded rows, 2 CTAs/SM ----------------
#define FA_TILE  18432
#define FA_STG   (2*FA_TILE)
#define FA_SMEM  (2*FA_STG)    // 73728
#define MASKV_   (-50.0f)

__global__ void __launch_bounds__(128, 2)
flash_mma_kernel() {
    extern __shared__ char smem[];
    uint32_t sb = smem_u32(smem);

    int b = blockIdx.z, h = blockIdx.y;
    int q0 = (gridDim.x - 1 - blockIdx.x) * 128;
    int kvh = h >> 2;
    int tid = threadIdx.x;
    int wid = tid >> 5, lane = tid & 31;
    int r = lane >> 2, c2 = (lane & 3) * 2;
    int lrow = (lane & 7) + ((lane >> 3) & 1) * 8;
    int lcol = (lane >> 4) * 8;

    int wq = wid * 32;
    int qmaxw = q0 + wq + 31;

    size_t tok[2][2];
    #pragma unroll
    for (int mf = 0; mf < 2; mf++) {
        tok[mf][0] = (size_t)(b * S_) + q0 + wq + mf * 16 + r;
        tok[mf][1] = tok[mf][0] + 8;
    }

    uint32_t qf[2][4][4];
    #pragma unroll
    for (int mf = 0; mf < 2; mf++)
        #pragma unroll
        for (int t = 0; t < 4; t++) {
            size_t c0 = (size_t)h * 64 + t * 16 + c2;
            qf[mf][t][0] = *(const uint32_t*)&g_qf[tok[mf][0] * 1024 + c0];
            qf[mf][t][1] = *(const uint32_t*)&g_qf[tok[mf][1] * 1024 + c0];
            qf[mf][t][2] = *(const uint32_t*)&g_qf[tok[mf][0] * 1024 + c0 + 8];
            qf[mf][t][3] = *(const uint32_t*)&g_qf[tok[mf][1] * 1024 + c0 + 8];
        }

    float oc[2][8][4];
    #pragma unroll
    for (int mf = 0; mf < 2; mf++)
        #pragma unroll
        for (int j = 0; j < 8; j++)
            #pragma unroll
            for (int p = 0; p < 4; p++) oc[mf][j][p] = 0.f;
    float lrw[2][2] = {{0.f, 0.f}, {0.f, 0.f}};

    const ull MAGIC2  = pk2(12582912.f, 12582912.f);
    const ull NMAGIC2 = pk2(-12582912.f, -12582912.f);
    const ull NONE2   = pk2(-1.f, -1.f);
    const ull ONE2    = pk2(1.f, 1.f);
    const ull EC1 = pk2(0.69314718f,  0.69314718f);
    const ull EC2 = pk2(0.24022651f,  0.24022651f);
    const ull EC3 = pk2(0.055504109f, 0.055504109f);
    const ull EC4 = pk2(0.0096181291f, 0.0096181291f);

    auto exp2pair = [&](float y0, float y1, float& e0, float& e1) {
        ull y = pk2(y0, y1);
        ull t = add2_(y, MAGIC2);
        ull rr_ = add2_(t, NMAGIC2);
        ull f = fma2_(rr_, NONE2, y);
        ull p = fma2_(EC4, f, EC3);
        p = fma2_(p, f, EC2);
        p = fma2_(p, f, EC1);
        p = fma2_(p, f, ONE2);
        uint32_t tl, th; up2u(tl, th, t);
        ull es = pk2u((tl << 23) + 0x3F800000u, (th << 23) + 0x3F800000u);
        ull res = mul2_(p, es);
        up2(e0, e1, res);
    };

    int q8 = tid & 7, rr = tid >> 3;

    auto load_tile = [&](int j0, int s) {
        #pragma unroll
        for (int p = 0; p < 8; p++) {
            int row = p * 16 + rr;
            size_t gsrc = (size_t)(b * S_ + j0 + row) * 256 + kvh * 64 + q8 * 8;
            CP_ASYNC16(sb + s * FA_STG + row * 144 + q8 * 16, g_kf + gsrc);
            CP_ASYNC16(sb + s * FA_STG + FA_TILE + row * 144 + q8 * 16, g_vf + gsrc);
        }
        CP_COMMIT();
    };

    load_tile(0, 0);

    for (int j0 = 0; j0 <= q0; j0 += 128) {
        int buf = (j0 >> 7) & 1;
        CP_WAIT(0);
        __syncthreads();
        if (j0 + 128 <= q0) load_tile(j0 + 128, buf ^ 1);

        uint32_t kbank = sb + buf * FA_STG;
        uint32_t vbank = kbank + FA_TILE;

        #pragma unroll
        for (int half = 0; half < 2; half++) {
            int kg0 = j0 + half * 64;
            bool active = (kg0 <= qmaxw);
            int ks = half * 64;

            if (active) {
                float sc[2][8][4];
                #pragma unroll
                for (int mf = 0; mf < 2; mf++)
                    #pragma unroll
                    for (int j = 0; j < 8; j++)
                        #pragma unroll
                        for (int p = 0; p < 4; p++) sc[mf][j][p] = 0.f;

                // scores = Q.K^T with bk register chain (prefetch 1 ahead)
                {
                    uint32_t bkb[2][4];
                    LDSM4(bkb[0], kbank + (ks + lrow) * 144 + lcol * 2);
                    #pragma unroll
                    for (int u = 0; u < 16; u++) {
                        int nt = u >> 2, t = u & 3;
                        int cur = u & 1;
                        if (u < 15) {
                            int un = u + 1;
                            int ntn = un >> 2, tn = un & 3;
                            LDSM4(bkb[cur ^ 1], kbank + (ks + ntn * 16 + lrow) * 144 + (tn * 16 + lcol) * 2);
                        }
                        #pragma unroll
                        for (int mf = 0; mf < 2; mf++) {
                            MMA_F16(sc[mf][nt*2],   qf[mf][t], bkb[cur][0], bkb[cur][2]);
                            MMA_F16(sc[mf][nt*2+1], qf[mf][t], bkb[cur][1], bkb[cur][3]);
                        }
                    }
                }

                if (kg0 + 63 > q0 + wq) {
                    #pragma unroll
                    for (int mf = 0; mf < 2; mf++) {
                        int qg0 = q0 + wq + mf * 16 + r;
                        int qg1 = qg0 + 8;
                        #pragma unroll
                        for (int j = 0; j < 8; j++) {
                            int key = kg0 + 8 * j + c2;
                            if (key     > qg0) sc[mf][j][0] = MASKV_;
                            if (key + 1 > qg0) sc[mf][j][1] = MASKV_;
                            if (key     > qg1) sc[mf][j][2] = MASKV_;
                            if (key + 1 > qg1) sc[mf][j][3] = MASKV_;
                        }
                    }
                }

                // p = exp2(s); pack to fp16 immediately
                uint32_t ph[2][8][2];
                #pragma unroll
                for (int mf = 0; mf < 2; mf++) {
                    float rs0 = 0.f, rs1 = 0.f;
                    #pragma unroll
                    for (int j = 0; j < 8; j++) {
                        float e0, e1, e2, e3;
                        exp2pair(sc[mf][j][0], sc[mf][j][1], e0, e1);
                        exp2pair(sc[mf][j][2], sc[mf][j][3], e2, e3);
                        rs0 += e0 + e1;
                        rs1 += e2 + e3;
                        ph[mf][j][0] = pkhf(e0, e1);
                        ph[mf][j][1] = pkhf(e2, e3);
                    }
                    lrw[mf][0] += rs0;
                    lrw[mf][1] += rs1;
                }

                // O += P @ V
                #pragma unroll
                for (int u = 0; u < 4; u++) {
                    #pragma unroll
                    for (int dv = 0; dv < 4; dv++) {
                        uint32_t vv[4];
                        LDSM4T(vv, vbank + (ks + u * 16 + (lane & 15)) * 144
                                   + (dv * 16 + (lane >> 4) * 8) * 2);
                        #pragma unroll
                        for (int mf = 0; mf < 2; mf++) {
                            uint32_t A0[4] = {ph[mf][2*u][0], ph[mf][2*u][1],
                                              ph[mf][2*u+1][0], ph[mf][2*u+1][1]};
                            MMA_F16(oc[mf][dv*2],   A0, vv[0], vv[1]);
                            MMA_F16(oc[mf][dv*2+1], A0, vv[2], vv[3]);
                        }
                    }
                }
            }
        }
    }

    #pragma unroll
    for (int mf = 0; mf < 2; mf++) {
        #pragma unroll
        for (int rh = 0; rh < 2; rh++) {
            float l = lrw[mf][rh];
            l += __shfl_xor_sync(0xffffffffu, l, 1);
            l += __shfl_xor_sync(0xffffffffu, l, 2);
            lrw[mf][rh] = 1.0f / l;
        }
        #pragma unroll
        for (int j = 0; j < 8; j++) {
            size_t col = (size_t)h * 64 + 8 * j + c2;
            *(uint32_t*)&g_yf[tok[mf][0] * 1024 + col] =
                pkhf(oc[mf][j][0] * lrw[mf][0], oc[mf][j][1] * lrw[mf][0]);
            *(uint32_t*)&g_yf[tok[mf][1] * 1024 + col] =
                pkhf(oc[mf][j][2] * lrw[mf][1], oc[mf][j][3] * lrw[mf][1]);
        }
    }
}

// ---------------- launch ----------------
extern "C" void kernel_launch(void* const* d_in, const int* in_sizes, int n_in,
                              void* d_out, int out_size) {
    const float* x    = (const float*)d_in[0];
    const float* Wq   = (const float*)d_in[1];
    const float* Wk   = (const float*)d_in[2];
    const float* Wv   = (const float*)d_in[3];
    const float* Wp   = (const float*)d_in[4];
    const float* gain = (const float*)d_in[5];
    const float* Aq   = (const float*)d_in[6];
    const float* Bq   = (const float*)d_in[7];
    const float* Av   = (const float*)d_in[8];
    const float* Bv   = (const float*)d_in[9];
    const int*   step = (const int*)d_in[10];
    float* out = (float*)d_out;

    prep_all_kernel<<<NBW_ + NBX_ + NBR_, 256>>>(x, Wq, Wk, Wv, Wp, Aq, Bq, Av, Bv, step);

    cudaFuncSetAttribute(gemm_mma_kernel<0>, cudaFuncAttributeMaxDynamicSharedMemorySize, G_SMEM);
    cudaFuncSetAttribute(gemm_mma_kernel<2>, cudaFuncAttributeMaxDynamicSharedMemorySize, G_SMEM);
    cudaFuncSetAttribute(flash_mma_kernel,   cudaFuncAttributeMaxDynamicSharedMemorySize, FA_SMEM);

    gemm_mma_kernel<0><<<dim3(1536/128, M_/128), 128, G_SMEM>>>(gain, nullptr);

    flash_mma_kernel<<<dim3(S_/128, H_, B_), 128, FA_SMEM>>>();

    gemm_mma_kernel<2><<<dim3(1024/128, M_/128), 128, G_SMEM>>>(gain, out);
}

// round 17
// speedup vs baseline: 1.6475x; 1.0611x over previous
#include <cuda_runtime.h>
#include <cuda_fp16.h>
#include <math.h>
#include <stdint.h>

#define B_      2
#define S_      2048
#define DIM_    1024
#define H_      16
#define KVH_    4
#define HD_     64
#define KVDIM_  256
#define R_      4
#define NSTEPS_ 2
#define M_      (B_*S_)
#define WROWS_  2560   // [0,1024): Wq+lora | [1024,1280): Wk | [1280,1536): Wv+lora | [1536,2560): Wp

#define QSCALE_ (0.125f * 1.4426950408889634f)

typedef unsigned short ushort_t;
typedef unsigned long long ull;

__device__ __forceinline__ uint32_t smem_u32(const void* p) {
    uint32_t a;
    asm("{ .reg .u64 t; cvta.to.shared.u64 t, %1; cvt.u32.u64 %0, t; }" : "=r"(a) : "l"(p));
    return a;
}

#define LDSM4(r, addr) \
    asm volatile("ldmatrix.sync.aligned.m8n8.x4.shared.b16 {%0,%1,%2,%3}, [%4];" \
        : "=r"((r)[0]),"=r"((r)[1]),"=r"((r)[2]),"=r"((r)[3]) : "r"(addr))
#define LDSM4T(r, addr) \
    asm volatile("ldmatrix.sync.aligned.m8n8.x4.trans.shared.b16 {%0,%1,%2,%3}, [%4];" \
        : "=r"((r)[0]),"=r"((r)[1]),"=r"((r)[2]),"=r"((r)[3]) : "r"(addr))

#define MMA_F16(c, a, b0v, b1v) \
    asm volatile("mma.sync.aligned.m16n8k16.row.col.f32.f16.f16.f32 " \
        "{%0,%1,%2,%3}, {%4,%5,%6,%7}, {%8,%9}, {%0,%1,%2,%3};" \
        : "+f"((c)[0]),"+f"((c)[1]),"+f"((c)[2]),"+f"((c)[3]) \
        : "r"((a)[0]),"r"((a)[1]),"r"((a)[2]),"r"((a)[3]), "r"(b0v),"r"(b1v))

#define CP_ASYNC16(dst, src) \
    asm volatile("cp.async.cg.shared.global [%0], [%1], 16;" :: "r"(dst), "l"(src) : "memory")
#define CP_COMMIT() asm volatile("cp.async.commit_group;" ::: "memory")
#define CP_WAIT(n)  asm volatile("cp.async.wait_group %0;" :: "n"(n) : "memory")

__device__ __forceinline__ uint32_t pkhf(float lo, float hi) {
    uint32_t r; asm("cvt.rn.f16x2.f32 %0, %1, %2;" : "=r"(r) : "f"(hi), "f"(lo)); return r;
}

// ---- packed f32x2 helpers ----
__device__ __forceinline__ ull pk2(float x, float y) {
    ull r; asm("mov.b64 %0, {%1, %2};" : "=l"(r) : "f"(x), "f"(y)); return r;
}
__device__ __forceinline__ ull pk2u(uint32_t x, uint32_t y) {
    ull r; asm("mov.b64 %0, {%1, %2};" : "=l"(r) : "r"(x), "r"(y)); return r;
}
__device__ __forceinline__ void up2(float& x, float& y, ull v) {
    asm("mov.b64 {%0, %1}, %2;" : "=f"(x), "=f"(y) : "l"(v));
}
__device__ __forceinline__ void up2u(uint32_t& x, uint32_t& y, ull v) {
    asm("mov.b64 {%0, %1}, %2;" : "=r"(x), "=r"(y) : "l"(v));
}
__device__ __forceinline__ ull add2_(ull a, ull b) {
    ull d; asm("add.rn.f32x2 %0, %1, %2;" : "=l"(d) : "l"(a), "l"(b)); return d;
}
__device__ __forceinline__ ull mul2_(ull a, ull b) {
    ull d; asm("mul.rn.f32x2 %0, %1, %2;" : "=l"(d) : "l"(a), "l"(b)); return d;
}
__device__ __forceinline__ ull fma2_(ull a, ull b, ull c) {
    ull d; asm("fma.rn.f32x2 %0, %1, %2, %3;" : "=l"(d) : "l"(a), "l"(b), "l"(c)); return d;
}

// ---------------- scratch ----------------
__device__ ushort_t g_xf[M_*DIM_];
__device__ ushort_t g_yf[M_*DIM_];
__device__ ushort_t g_whf[WROWS_*DIM_];
__device__ ushort_t g_qf[M_*DIM_];
__device__ ushort_t g_kf[M_*KVDIM_];
__device__ ushort_t g_vf[M_*KVDIM_];
__device__ float    g_rope[S_*16*2];   // [s][i] -> (cos, sin)

// ---------------- fused prep ----------------
#define NBW_ ((WROWS_*256)/256)
#define NBX_ ((M_*DIM_/4)/256)
#define NBR_ ((S_*16+255)/256)
__global__ void prep_all_kernel(const float* __restrict__ x,
                                const float* __restrict__ Wq, const float* __restrict__ Wk,
                                const float* __restrict__ Wv, const float* __restrict__ Wp,
                                const float* __restrict__ Aq, const float* __restrict__ Bq,
                                const float* __restrict__ Av, const float* __restrict__ Bv,
                                const int*   __restrict__ stepp) {
    int blk = blockIdx.x;
    if (blk < NBW_) {
        int t = blk * 256 + threadIdx.x;
        int row = t >> 8, k4 = t & 255;
        int step = *stepp;
        bool ok = (step >= 0 && step < NSTEPS_);
        float4 w;
        if (row < 1024) {
            w = ((const float4*)(Wq + (size_t)row * DIM_))[k4];
            if (ok) {
                const float* Ab = Aq + (size_t)step * R_ * DIM_;
                const float* Bb = Bq + ((size_t)step * DIM_ + row) * R_;
                #pragma unroll
                for (int r = 0; r < R_; r++) {
                    float b = Bb[r];
                    float4 a = ((const float4*)(Ab + (size_t)r * DIM_))[k4];
                    w.x += b*a.x; w.y += b*a.y; w.z += b*a.z; w.w += b*a.w;
                }
            }
        } else if (row < 1280) {
            w = ((const float4*)(Wk + (size_t)(row - 1024) * DIM_))[k4];
        } else if (row < 1536) {
            int vr = row - 1280;
            w = ((const float4*)(Wv + (size_t)vr * DIM_))[k4];
            if (ok) {
                const float* Ab = Av + (size_t)step * R_ * DIM_;
                const float* Bb = Bv + ((size_t)step * KVDIM_ + vr) * R_;
                #pragma unroll
                for (int r = 0; r < R_; r++) {
                    float b = Bb[r];
                    float4 a = ((const float4*)(Ab + (size_t)r * DIM_))[k4];
                    w.x += b*a.x; w.y += b*a.y; w.z += b*a.z; w.w += b*a.w;
                }
            }
        } else {
            w = ((const float4*)(Wp + (size_t)(row - 1536) * DIM_))[k4];
        }
        uint2 hp;
        hp.x = pkhf(w.x, w.y);
        hp.y = pkhf(w.z, w.w);
        ((uint2*)g_whf)[t] = hp;
    } else if (blk < NBW_ + NBX_) {
        int t = (blk - NBW_) * 256 + threadIdx.x;
        float4 v = ((const float4*)x)[t];
        uint2 o;
        o.x = pkhf(v.x, v.y);
        o.y = pkhf(v.z, v.w);
        ((uint2*)g_xf)[t] = o;
    } else {
        int t = (blk - NBW_ - NBX_) * 256 + threadIdx.x;
        if (t < S_ * 16) {
            int s = t >> 4, i = t & 15;
            float invf = exp2f(-0.83048202372184059f * (float)i);
            float ang = (float)s * invf;
            g_rope[t * 2]     = cosf(ang);
            g_rope[t * 2 + 1] = sinf(ang);
        }
    }
}

// ---------------- fp16 GEMM, 3 stages, 3 CTAs/SM, fused RMS+RoPE epilogue ----------------
#define GT_      10240            // 128 rows x 80B
#define GSTAGE_  (2*GT_)
#define G_SMEM   (3*GSTAGE_)      // 61440 -> 3 CTAs/SM

template<int MODE>
__global__ void __launch_bounds__(128, 3)
gemm_mma_kernel(const float* __restrict__ gainp, float* __restrict__ outp) {
    extern __shared__ char smem[];
    uint32_t sb = smem_u32(smem);
    constexpr int WOFF = (MODE == 0) ? 0 : 1536;
    const ushort_t* Xf = (MODE == 2) ? g_yf : g_xf;

    int m0 = blockIdx.y * 128, n0 = blockIdx.x * 128;
    int tid = threadIdx.x;
    int wid = tid >> 5, lane = tid & 31;
    int wm = (wid >> 1) * 64, wn = (wid & 1) * 64;
    int lrow = (lane & 7) + ((lane >> 3) & 1) * 8;
    int lcol = (lane >> 4) * 8;

    auto load_stage = [&](int it, int s) {
        int k0 = it * 32;
        int q = tid & 3;
        int r0 = tid >> 2;
        #pragma unroll
        for (int t = 0; t < 8; t++) {
            int tile = t >> 2;
            int row = (t & 3) * 32 + r0;
            const ushort_t* src;
            if (tile == 0) src = Xf    + (size_t)(m0 + row) * DIM_ + k0 + q * 8;
            else           src = g_whf + (size_t)(WOFF + n0 + row) * DIM_ + k0 + q * 8;
            CP_ASYNC16(sb + s * GSTAGE_ + tile * GT_ + row * 80 + q * 16, src);
        }
        CP_COMMIT();
    };

    float c[4][8][4];
    #pragma unroll
    for (int i = 0; i < 4; i++)
        #pragma unroll
        for (int j = 0; j < 8; j++)
            #pragma unroll
            for (int p = 0; p < 4; p++) c[i][j][p] = 0.f;

    load_stage(0, 0);
    load_stage(1, 1);

    int slot = 2;
    for (int it = 0; it < 32; it++) {
        if (it < 31) CP_WAIT(1);
        else         CP_WAIT(0);
        __syncthreads();
        if (it + 2 < 32) load_stage(it + 2, slot);
        if (++slot == 3) slot = 0;

        uint32_t base = sb + (it % 3) * GSTAGE_;

        #pragma unroll
        for (int ks = 0; ks < 2; ks++) {
            int kb = ks * 16;
            uint32_t a[4][4];
            #pragma unroll
            for (int mf = 0; mf < 4; mf++)
                LDSM4(a[mf], base + (wm + mf * 16 + lrow) * 80 + (kb + lcol) * 2);
            uint32_t bb[2][4];
            LDSM4(bb[0], base + GT_ + (wn + lrow) * 80 + (kb + lcol) * 2);
            #pragma unroll
            for (int nt = 0; nt < 4; nt++) {
                int cur = nt & 1;
                if (nt < 3)
                    LDSM4(bb[cur ^ 1], base + GT_ + (wn + (nt+1) * 16 + lrow) * 80 + (kb + lcol) * 2);
                #pragma unroll
                for (int mf = 0; mf < 4; mf++) {
                    MMA_F16(c[mf][nt*2],   a[mf], bb[cur][0], bb[cur][2]);
                    MMA_F16(c[mf][nt*2+1], a[mf], bb[cur][1], bb[cur][3]);
                }
            }
        }
    }

    if (MODE == 2) {
        #pragma unroll
        for (int mf = 0; mf < 4; mf++) {
            #pragma unroll
            for (int nf = 0; nf < 8; nf++) {
                int gr = m0 + wm + mf * 16 + (lane >> 2);
                int gc = n0 + wn + nf * 8 + (lane & 3) * 2;
                *(float2*)&outp[(size_t)gr * 1024 + gc]       = make_float2(c[mf][nf][0], c[mf][nf][1]);
                *(float2*)&outp[(size_t)(gr + 8) * 1024 + gc] = make_float2(c[mf][nf][2], c[mf][nf][3]);
            }
        }
        return;
    }

    int nglob = n0 + wn;
    if (nglob >= 1280) {
        #pragma unroll
        for (int mf = 0; mf < 4; mf++) {
            #pragma unroll
            for (int nf = 0; nf < 8; nf++) {
                int gr = m0 + wm + mf * 16 + (lane >> 2);
                int vc = nglob - 1280 + nf * 8 + (lane & 3) * 2;
                *(uint32_t*)&g_vf[(size_t)gr * 256 + vc]       = pkhf(c[mf][nf][0], c[mf][nf][1]);
                *(uint32_t*)&g_vf[(size_t)(gr + 8) * 256 + vc] = pkhf(c[mf][nf][2], c[mf][nf][3]);
            }
        }
        return;
    }

    bool isQ = (nglob < 1024);
    float gsc = isQ ? (gainp[nglob >> 6] * QSCALE_) : 1.0f;
    int q2 = (lane & 3) * 2;

    #pragma unroll
    for (int mf = 0; mf < 4; mf++) {
        #pragma unroll
        for (int rr = 0; rr < 2; rr++) {
            float v[8][2];
            #pragma unroll
            for (int nf = 0; nf < 8; nf++) {
                v[nf][0] = c[mf][nf][rr * 2];
                v[nf][1] = c[mf][nf][rr * 2 + 1];
            }
            float ss = 0.f;
            #pragma unroll
            for (int nf = 0; nf < 8; nf++)
                ss += v[nf][0] * v[nf][0] + v[nf][1] * v[nf][1];
            ss += __shfl_xor_sync(0xffffffffu, ss, 1);
            ss += __shfl_xor_sync(0xffffffffu, ss, 2);
            float scl = rsqrtf(ss * (1.0f / 64.0f) + 1.1920929e-7f) * gsc;
            #pragma unroll
            for (int nf = 0; nf < 8; nf++) { v[nf][0] *= scl; v[nf][1] *= scl; }

            int m = m0 + wm + mf * 16 + (lane >> 2) + rr * 8;
            int s = m & (S_ - 1);
            float4 r0 = *(const float4*)&g_rope[(s * 16 + q2) * 2];
            float4 r1 = *(const float4*)&g_rope[(s * 16 + 8 + q2) * 2];
            float x1, x2;
            x1 = v[0][0]; x2 = v[2][0];
            v[0][0] = x1 * r0.x + x2 * r0.y;  v[2][0] = -x1 * r0.y + x2 * r0.x;
            x1 = v[0][1]; x2 = v[2][1];
            v[0][1] = x1 * r0.z + x2 * r0.w;  v[2][1] = -x1 * r0.w + x2 * r0.z;
            x1 = v[1][0]; x2 = v[3][0];
            v[1][0] = x1 * r1.x + x2 * r1.y;  v[3][0] = -x1 * r1.y + x2 * r1.x;
            x1 = v[1][1]; x2 = v[3][1];
            v[1][1] = x1 * r1.z + x2 * r1.w;  v[3][1] = -x1 * r1.w + x2 * r1.z;

            if (isQ) {
                size_t bix = (size_t)m * 1024 + nglob + q2;
                #pragma unroll
                for (int nf = 0; nf < 8; nf++)
                    *(uint32_t*)&g_qf[bix + nf * 8] = pkhf(v[nf][0], v[nf][1]);
            } else {
                size_t bix = (size_t)m * 256 + (nglob - 1024) + q2;
                #pragma unroll
                for (int nf = 0; nf < 8; nf++)
                    *(uint32_t*)&g_kf[bix + nf * 8] = pkhf(v[nf][0], v[nf][1]);
            }
        }
    }
}

// ---------------- flash attention: balanced q-tile pairs, 2 CTAs/SM ----------------
#define FA_TILE  18432
#define FA_STG   (2*FA_TILE)
#define FA_SMEM  (2*FA_STG)    // 73728
#define MASKV_   (-50.0f)
#define NQT_     (S_/128)      // 16 q-tiles

__global__ void __launch_bounds__(128, 2)
flash_mma_kernel() {
    extern __shared__ char smem[];
    uint32_t sb = smem_u32(smem);

    int b = blockIdx.z, h = blockIdx.y;
    int kvh = h >> 2;
    int tid = threadIdx.x;
    int wid = tid >> 5, lane = tid & 31;
    int r = lane >> 2, c2 = (lane & 3) * 2;
    int lrow = (lane & 7) + ((lane >> 3) & 1) * 8;
    int lcol = (lane >> 4) * 8;
    int wq = wid * 32;
    int q8 = tid & 7, rr = tid >> 3;

    const ull MAGIC2  = pk2(12582912.f, 12582912.f);
    const ull NMAGIC2 = pk2(-12582912.f, -12582912.f);
    const ull NONE2   = pk2(-1.f, -1.f);
    const ull ONE2    = pk2(1.f, 1.f);
    const ull EC1 = pk2(0.69314718f,  0.69314718f);
    const ull EC2 = pk2(0.24022651f,  0.24022651f);
    const ull EC3 = pk2(0.055504109f, 0.055504109f);
    const ull EC4 = pk2(0.0096181291f, 0.0096181291f);

    auto exp2pair = [&](float y0, float y1, float& e0, float& e1) {
        ull y = pk2(y0, y1);
        ull t = add2_(y, MAGIC2);
        ull rr_ = add2_(t, NMAGIC2);
        ull f = fma2_(rr_, NONE2, y);
        ull p = fma2_(EC4, f, EC3);
        p = fma2_(p, f, EC2);
        p = fma2_(p, f, EC1);
        p = fma2_(p, f, ONE2);
        uint32_t tl, th; up2u(tl, th, t);
        ull es = pk2u((tl << 23) + 0x3F800000u, (th << 23) + 0x3F800000u);
        ull res = mul2_(p, es);
        up2(e0, e1, res);
    };

    auto load_tile = [&](int j0, int s) {
        #pragma unroll
        for (int p = 0; p < 8; p++) {
            int row = p * 16 + rr;
            size_t gsrc = (size_t)(b * S_ + j0 + row) * 256 + kvh * 64 + q8 * 8;
            CP_ASYNC16(sb + s * FA_STG + row * 144 + q8 * 16, g_kf + gsrc);
            CP_ASYNC16(sb + s * FA_STG + FA_TILE + row * 144 + q8 * 16, g_vf + gsrc);
        }
        CP_COMMIT();
    };

    // paired q-tiles: CTA x handles tile (NQT_-1-x) then tile x -> 17 key-tiles each
    #pragma unroll 1
    for (int pass = 0; pass < 2; pass++) {
        int qt = (pass == 0) ? (NQT_ - 1 - (int)blockIdx.x) : (int)blockIdx.x;
        int q0 = qt * 128;
        int qmaxw = q0 + wq + 31;

        size_t tok[2][2];
        #pragma unroll
        for (int mf = 0; mf < 2; mf++) {
            tok[mf][0] = (size_t)(b * S_) + q0 + wq + mf * 16 + r;
            tok[mf][1] = tok[mf][0] + 8;
        }

        uint32_t qf[2][4][4];
        #pragma unroll
        for (int mf = 0; mf < 2; mf++)
            #pragma unroll
            for (int t = 0; t < 4; t++) {
                size_t c0 = (size_t)h * 64 + t * 16 + c2;
                qf[mf][t][0] = *(const uint32_t*)&g_qf[tok[mf][0] * 1024 + c0];
                qf[mf][t][1] = *(const uint32_t*)&g_qf[tok[mf][1] * 1024 + c0];
                qf[mf][t][2] = *(const uint32_t*)&g_qf[tok[mf][0] * 1024 + c0 + 8];
                qf[mf][t][3] = *(const uint32_t*)&g_qf[tok[mf][1] * 1024 + c0 + 8];
            }

        float oc[2][8][4];
        #pragma unroll
        for (int mf = 0; mf < 2; mf++)
            #pragma unroll
            for (int j = 0; j < 8; j++)
                #pragma unroll
                for (int p = 0; p < 4; p++) oc[mf][j][p] = 0.f;
        float lrw[2][2] = {{0.f, 0.f}, {0.f, 0.f}};

        load_tile(0, 0);

        for (int j0 = 0; j0 <= q0; j0 += 128) {
            int buf = (j0 >> 7) & 1;
            CP_WAIT(0);
            __syncthreads();
            if (j0 + 128 <= q0) load_tile(j0 + 128, buf ^ 1);

            uint32_t kbank = sb + buf * FA_STG;
            uint32_t vbank = kbank + FA_TILE;

            #pragma unroll
            for (int half = 0; half < 2; half++) {
                int kg0 = j0 + half * 64;
                bool active = (kg0 <= qmaxw);
                int ks = half * 64;

                if (active) {
                    float sc[2][8][4];
                    #pragma unroll
                    for (int mf = 0; mf < 2; mf++)
                        #pragma unroll
                        for (int j = 0; j < 8; j++)
                            #pragma unroll
                            for (int p = 0; p < 4; p++) sc[mf][j][p] = 0.f;

                    // scores = Q.K^T with bk register chain (prefetch 1 ahead)
                    {
                        uint32_t bkb[2][4];
                        LDSM4(bkb[0], kbank + (ks + lrow) * 144 + lcol * 2);
                        #pragma unroll
                        for (int u = 0; u < 16; u++) {
                            int nt = u >> 2, t = u & 3;
                            int cur = u & 1;
                            if (u < 15) {
                                int un = u + 1;
                                int ntn = un >> 2, tn = un & 3;
                                LDSM4(bkb[cur ^ 1], kbank + (ks + ntn * 16 + lrow) * 144 + (tn * 16 + lcol) * 2);
                            }
                            #pragma unroll
                            for (int mf = 0; mf < 2; mf++) {
                                MMA_F16(sc[mf][nt*2],   qf[mf][t], bkb[cur][0], bkb[cur][2]);
                                MMA_F16(sc[mf][nt*2+1], qf[mf][t], bkb[cur][1], bkb[cur][3]);
                            }
                        }
                    }

                    if (kg0 + 63 > q0 + wq) {
                        #pragma unroll
                        for (int mf = 0; mf < 2; mf++) {
                            int qg0 = q0 + wq + mf * 16 + r;
                            int qg1 = qg0 + 8;
                            #pragma unroll
                            for (int j = 0; j < 8; j++) {
                                int key = kg0 + 8 * j + c2;
                                if (key     > qg0) sc[mf][j][0] = MASKV_;
                                if (key + 1 > qg0) sc[mf][j][1] = MASKV_;
                                if (key     > qg1) sc[mf][j][2] = MASKV_;
                                if (key + 1 > qg1) sc[mf][j][3] = MASKV_;
                            }
                        }
                    }

                    // p = exp2(s); pack to fp16 immediately
                    uint32_t ph[2][8][2];
                    #pragma unroll
                    for (int mf = 0; mf < 2; mf++) {
                        float rs0 = 0.f, rs1 = 0.f;
                        #pragma unroll
                        for (int j = 0; j < 8; j++) {
                            float e0, e1, e2, e3;
                            exp2pair(sc[mf][j][0], sc[mf][j][1], e0, e1);
                            exp2pair(sc[mf][j][2], sc[mf][j][3], e2, e3);
                            rs0 += e0 + e1;
                            rs1 += e2 + e3;
                            ph[mf][j][0] = pkhf(e0, e1);
                            ph[mf][j][1] = pkhf(e2, e3);
                        }
                        lrw[mf][0] += rs0;
                        lrw[mf][1] += rs1;
                    }

                    // O += P @ V
                    #pragma unroll
                    for (int u = 0; u < 4; u++) {
                        #pragma unroll
                        for (int dv = 0; dv < 4; dv++) {
                            uint32_t vv[4];
                            LDSM4T(vv, vbank + (ks + u * 16 + (lane & 15)) * 144
                                       + (dv * 16 + (lane >> 4) * 8) * 2);
                            #pragma unroll
                            for (int mf = 0; mf < 2; mf++) {
                                uint32_t A0[4] = {ph[mf][2*u][0], ph[mf][2*u][1],
                                                  ph[mf][2*u+1][0], ph[mf][2*u+1][1]};
                                MMA_F16(oc[mf][dv*2],   A0, vv[0], vv[1]);
                                MMA_F16(oc[mf][dv*2+1], A0, vv[2], vv[3]);
                            }
                        }
                    }
                }
            }
        }

        // epilogue for this q-tile
        #pragma unroll
        for (int mf = 0; mf < 2; mf++) {
            #pragma unroll
            for (int rh = 0; rh < 2; rh++) {
                float l = lrw[mf][rh];
                l += __shfl_xor_sync(0xffffffffu, l, 1);
                l += __shfl_xor_sync(0xffffffffu, l, 2);
                lrw[mf][rh] = 1.0f / l;
            }
            #pragma unroll
            for (int j = 0; j < 8; j++) {
                size_t col = (size_t)h * 64 + 8 * j + c2;
                *(uint32_t*)&g_yf[tok[mf][0] * 1024 + col] =
                    pkhf(oc[mf][j][0] * lrw[mf][0], oc[mf][j][1] * lrw[mf][0]);
                *(uint32_t*)&g_yf[tok[mf][1] * 1024 + col] =
                    pkhf(oc[mf][j][2] * lrw[mf][1], oc[mf][j][3] * lrw[mf][1]);
            }
        }
        __syncthreads();   // pass A smem fully consumed before pass B loads
    }
}

// ---------------- launch ----------------
extern "C" void kernel_launch(void* const* d_in, const int* in_sizes, int n_in,
                              void* d_out, int out_size) {
    const float* x    = (const float*)d_in[0];
    const float* Wq   = (const float*)d_in[1];
    const float* Wk   = (const float*)d_in[2];
    const float* Wv   = (const float*)d_in[3];
    const float* Wp   = (const float*)d_in[4];
    const float* gain = (const float*)d_in[5];
    const float* Aq   = (const float*)d_in[6];
    const float* Bq   = (const float*)d_in[7];
    const float* Av   = (const float*)d_in[8];
    const float* Bv   = (const float*)d_in[9];
    const int*   step = (const int*)d_in[10];
    float* out = (float*)d_out;

    prep_all_kernel<<<NBW_ + NBX_ + NBR_, 256>>>(x, Wq, Wk, Wv, Wp, Aq, Bq, Av, Bv, step);

    cudaFuncSetAttribute(gemm_mma_kernel<0>, cudaFuncAttributeMaxDynamicSharedMemorySize, G_SMEM);
    cudaFuncSetAttribute(gemm_mma_kernel<2>, cudaFuncAttributeMaxDynamicSharedMemorySize, G_SMEM);
    cudaFuncSetAttribute(flash_mma_kernel,   cudaFuncAttributeMaxDynamicSharedMemorySize, FA_SMEM);

    gemm_mma_kernel<0><<<dim3(1536/128, M_/128), 128, G_SMEM>>>(gain, nullptr);

    flash_mma_kernel<<<dim3(NQT_/2, H_, B_), 128, FA_SMEM>>>();

    gemm_mma_kernel<2><<<dim3(1024/128, M_/128), 128, G_SMEM>>>(gain, out);
}